// round 15
// baseline (speedup 1.0000x reference)
#include <cuda_runtime.h>
#include <cuda_fp16.h>
#include <cstdint>

// Problem constants
#define BB   8
#define NN   8192
#define SS   2048
#define C1K  128
#define C2K  256
#define INCH 384            // C1 + C2
#define H1   256
#define H2   128
#define MM   (BB * NN)      // 65536 total points

// ---------------- scratch (static device globals; no allocation) ----------------
__device__ __half g_Xh [MM * (size_t)INCH];          // fp16-rounded concat(p1, interp)
__device__ __half g_W1h[H1 * INCH];
__device__ __half g_W2h[H2 * H1];
__device__ float g_Y1 [MM * (size_t)H1];
__device__ float g_Y2 [MM * (size_t)H2];
__device__ float g_P2T[BB * (size_t)SS * C2K];       // fp32 transposed points2
__device__ int   g_idx[MM * 3];
__device__ float g_wt [MM * 3];
__device__ float g_sum1[H1], g_sq1[H1], g_sum2[H2], g_sq2[H2];
__device__ float g_sc1 [H1], g_sh1[H1], g_sc2 [H2], g_sh2[H2];

// ---------------- PTX helpers (baseline sm_103 features only) ----------------
#define LDSM_X4(r0, r1, r2, r3, addr) \
    asm volatile("ldmatrix.sync.aligned.m8n8.x4.shared.b16 {%0,%1,%2,%3}, [%4];" \
        : "=r"(r0), "=r"(r1), "=r"(r2), "=r"(r3) : "r"(addr))

#define MMA_F16(d, a0, a1, a2, a3, b0, b1) \
    asm volatile("mma.sync.aligned.m16n8k16.row.col.f32.f16.f16.f32 " \
        "{%0,%1,%2,%3}, {%4,%5,%6,%7}, {%8,%9}, {%0,%1,%2,%3};" \
        : "+f"((d)[0]), "+f"((d)[1]), "+f"((d)[2]), "+f"((d)[3]) \
        : "r"(a0), "r"(a1), "r"(a2), "r"(a3), "r"(b0), "r"(b1))

#define CP16(dst, src) \
    asm volatile("cp.async.cg.shared.global [%0], [%1], 16;" :: "r"(dst), "l"(src) : "memory")
#define CPC() asm volatile("cp.async.commit_group;" ::: "memory")
#define CPW(n) asm volatile("cp.async.wait_group %0;" :: "n"(n) : "memory")

__device__ __forceinline__ uint32_t smem_to_u32(const void* p) {
    uint32_t a;
    asm("{ .reg .u64 t; cvta.to.shared.u64 t, %1; cvt.u32.u64 %0, t; }" : "=r"(a) : "l"(p));
    return a;
}
__device__ __forceinline__ uint32_t pack_h2(__half a, __half b) {
    __half2 v(a, b);
    return *(uint32_t*)&v;
}

// ================= fused producer kernel (R13 layout) =================
// blocks [0,512):      weight fp16 rounds + stats zero
// blocks [512,4608):   points2 [B,256,S] -> P2T [B,S,256] fp32 transpose
// blocks [4608,12800): points1 [B,128,N] -> Xh cols 0:128 (fp16 round)
__global__ __launch_bounds__(256) void prep_kernel(
    const float* __restrict__ W1, const float* __restrict__ W2,
    const float* __restrict__ points1, const float* __restrict__ points2)
{
    __shared__ float tile[32][33];
    int bx = blockIdx.x;
    int tid = threadIdx.x;
    if (bx < 512) {
        if (bx == 0) {
            g_sum1[tid] = 0.f; g_sq1[tid] = 0.f;
            if (tid < H2) { g_sum2[tid] = 0.f; g_sq2[tid] = 0.f; }
        }
        int i = bx * 256 + tid;
        if (i < H1 * INCH) {
            g_W1h[i] = __float2half(W1[i]);
        } else {
            int j = i - H1 * INCH;
            g_W2h[j] = __float2half(W2[j]);
        }
        return;
    }
    int tx = tid & 31, ty = tid >> 5;
    if (bx < 4608) {
        int t = bx - 512;
        int b = t >> 9, rem = t & 511;
        int l0 = (rem & 63) * 32, c0 = (rem >> 6) * 32;
        const float* s = points2 + (size_t)b * C2K * SS;
        float* d = g_P2T + (size_t)b * SS * C2K;
#pragma unroll
        for (int i = 0; i < 4; i++)
            tile[ty + i * 8][tx] = s[(size_t)(c0 + ty + i * 8) * SS + l0 + tx];
        __syncthreads();
#pragma unroll
        for (int i = 0; i < 4; i++)
            d[(size_t)(l0 + ty + i * 8) * C2K + c0 + tx] = tile[tx][ty + i * 8];
    } else {
        int t = bx - 4608;
        int b = t >> 10, rem = t & 1023;
        int l0 = (rem & 255) * 32, c0 = (rem >> 8) * 32;
        const float* s = points1 + (size_t)b * C1K * NN;
#pragma unroll
        for (int i = 0; i < 4; i++)
            tile[ty + i * 8][tx] = s[(size_t)(c0 + ty + i * 8) * NN + l0 + tx];
        __syncthreads();
#pragma unroll
        for (int i = 0; i < 4; i++) {
            int l = l0 + ty + i * 8;
            size_t o = ((size_t)b * NN + l) * INCH + c0 + tx;
            g_Xh[o] = __float2half(tile[tx][ty + i * 8]);
        }
    }
}

// ---------------- 3-NN, smem resident, dual interleaved trackers (fp32) ------
__global__ void knn_kernel(const float* __restrict__ xyz1, const float* __restrict__ xyz2)
{
    __shared__ float4 sq[SS];
    int b = blockIdx.y;
    const float* x2 = xyz2 + (size_t)b * 3 * SS;
    for (int s = threadIdx.x; s < SS; s += blockDim.x) {
        float qx = x2[s], qy = x2[SS + s], qz = x2[2 * SS + s];
        sq[s] = make_float4(qx, qy, qz, qx * qx + qy * qy + qz * qz);
    }
    __syncthreads();

    int n = blockIdx.x * blockDim.x + threadIdx.x;
    const float* x1 = xyz1 + (size_t)b * 3 * NN;
    float px = x1[n], py = x1[NN + n], pz = x1[2 * NN + n];
    float mx = -2.f * px, my = -2.f * py, mz = -2.f * pz;
    float p2 = px * px + py * py + pz * pz;

    float a0 = 1e30f, a1 = 1e30f, a2 = 1e30f;
    float c0 = 1e30f, c1 = 1e30f, c2 = 1e30f;
    int   ia0 = 0, ia1 = 0, ia2 = 0, ib0 = 0, ib1 = 0, ib2 = 0;

#pragma unroll 4
    for (int s = 0; s < SS / 2; s++) {
        float4 qa = sq[s];
        float4 qb = sq[s + SS / 2];
        float tA = fmaf(mx, qa.x, fmaf(my, qa.y, fmaf(mz, qa.z, qa.w)));
        float tB = fmaf(mx, qb.x, fmaf(my, qb.y, fmaf(mz, qb.z, qb.w)));
        if (tA < a2) {
            if (tA < a1) {
                a2 = a1; ia2 = ia1;
                if (tA < a0) { a1 = a0; ia1 = ia0; a0 = tA; ia0 = s; }
                else         { a1 = tA; ia1 = s; }
            } else { a2 = tA; ia2 = s; }
        }
        if (tB < c2) {
            if (tB < c1) {
                c2 = c1; ib2 = ib1;
                if (tB < c0) { c1 = c0; ib1 = ib0; c0 = tB; ib0 = s + SS / 2; }
                else         { c1 = tB; ib1 = s + SS / 2; }
            } else { c2 = tB; ib2 = s + SS / 2; }
        }
    }
    float mv[3] = {c0, c1, c2};
    int   mi[3] = {ib0, ib1, ib2};
#pragma unroll
    for (int t = 0; t < 3; t++) {
        float v = mv[t]; int ix = mi[t];
        if (v < a2) {
            if (v < a1) {
                a2 = a1; ia2 = ia1;
                if (v < a0) { a1 = a0; ia1 = ia0; a0 = v; ia0 = ix; }
                else        { a1 = v;  ia1 = ix; }
            } else { a2 = v; ia2 = ix; }
        }
    }
    float e0 = a0 + p2, e1 = a1 + p2, e2 = a2 + p2;
    float r0 = 1.f / (e0 + 1e-8f), r1 = 1.f / (e1 + 1e-8f), r2 = 1.f / (e2 + 1e-8f);
    float rs = 1.f / (r0 + r1 + r2);
    size_t base = ((size_t)b * NN + n) * 3;
    g_idx[base] = ia0; g_idx[base + 1] = ia1; g_idx[base + 2] = ia2;
    g_wt [base] = r0 * rs; g_wt[base + 1] = r1 * rs; g_wt[base + 2] = r2 * rs;
}

// ---------------- weighted gather of 3 rows from P2T -> Xh[:,128:384] --------
__global__ void interp_kernel()
{
    int b  = blockIdx.y;
    int c  = threadIdx.x;
    int n0 = blockIdx.x * 32;
    const float* p2t = g_P2T + (size_t)b * SS * C2K;
#pragma unroll 4
    for (int r = 0; r < 32; r++) {
        size_t m = (size_t)b * NN + n0 + r;
        int   j0 = g_idx[m * 3], j1 = g_idx[m * 3 + 1], j2 = g_idx[m * 3 + 2];
        float w0 = g_wt[m * 3], w1 = g_wt[m * 3 + 1], w2 = g_wt[m * 3 + 2];
        float v = w0 * p2t[(size_t)j0 * C2K + c]
                + w1 * p2t[(size_t)j1 * C2K + c]
                + w2 * p2t[(size_t)j2 * C2K + c];
        g_Xh[m * INCH + C1K + c] = __float2half(v);
    }
}

// ================= mma.sync fp16 GEMM: CTA 128x64, warp tile 32x32, 3 CTAs/SM ==
// 8 warps (4m x 2n). C = Ah * Bh. Bias dropped (cancels in BN); column stats fused.
// AFBN: A source is fp32 Y1; BN1+ReLU+fp16-round applied in register staging.
template <int K, bool AFBN>
__global__ __launch_bounds__(256, 3) void tc_gemm_kernel(
    const void* __restrict__ Asrc,
    const __half* __restrict__ Bh,
    const float* __restrict__ sc, const float* __restrict__ sh,
    float* __restrict__ Y, int ldc,
    float* __restrict__ osum, float* __restrict__ osq)
{
    constexpr int NCH   = K / 32;
    constexpr int KR4   = K / 8;            // int4 per fp16 row
    constexpr int MATA  = 128 * 80;         // A smem bytes (padded)
    constexpr int MATB  = 64 * 80;          // B smem bytes (padded)
    constexpr int STAGE = MATA + MATB;

    extern __shared__ char smem[];
    uint32_t sb32 = smem_to_u32(smem);
    float* ssc = (float*)(smem + 2 * STAGE);
    float* ssh = ssc + K;

    int tid = threadIdx.x;
    int lane = tid & 31, wid = tid >> 5;
    int warpM = wid >> 1, warpN = wid & 1;  // 4 x 2
    int m0 = blockIdx.x * 128;
    int n0 = blockIdx.y * 64;

    const int4* gA = (const int4*)Asrc + (AFBN ? 0 : (size_t)m0 * KR4);
    const float4* gAf = (const float4*)Asrc + (size_t)m0 * (K / 4);
    const int4* gBh = (const int4*)Bh + (size_t)n0 * KR4;

    if (AFBN) {
        for (int i = tid; i < K; i += 256) { ssc[i] = sc[i]; ssh[i] = sh[i]; }
        __syncthreads();
    }

    int ldr = tid >> 2, ldc4 = tid & 3;     // A rows {ldr, ldr+64}; B row ldr (0..63)

    auto load_stage = [&](int c, int stage) {
        uint32_t s = sb32 + stage * STAGE;
        if (AFBN) {
            char* sp = smem + stage * STAGE;
            int k0 = c * 32 + ldc4 * 8;
            float4 s0 = *(const float4*)&ssc[k0], s1 = *(const float4*)&ssc[k0 + 4];
            float4 t0 = *(const float4*)&ssh[k0], t1 = *(const float4*)&ssh[k0 + 4];
#pragma unroll
            for (int it = 0; it < 2; it++) {
                int r = ldr + it * 64;
                float4 v0 = gAf[(size_t)r * (K / 4) + c * 8 + ldc4 * 2];
                float4 v1 = gAf[(size_t)r * (K / 4) + c * 8 + ldc4 * 2 + 1];
                uint32_t ph[4];
                ph[0] = pack_h2(__float2half(fmaxf(fmaf(v0.x, s0.x, t0.x), 0.f)),
                                __float2half(fmaxf(fmaf(v0.y, s0.y, t0.y), 0.f)));
                ph[1] = pack_h2(__float2half(fmaxf(fmaf(v0.z, s0.z, t0.z), 0.f)),
                                __float2half(fmaxf(fmaf(v0.w, s0.w, t0.w), 0.f)));
                ph[2] = pack_h2(__float2half(fmaxf(fmaf(v1.x, s1.x, t1.x), 0.f)),
                                __float2half(fmaxf(fmaf(v1.y, s1.y, t1.y), 0.f)));
                ph[3] = pack_h2(__float2half(fmaxf(fmaf(v1.z, s1.z, t1.z), 0.f)),
                                __float2half(fmaxf(fmaf(v1.w, s1.w, t1.w), 0.f)));
                *(int4*)(sp + r * 80 + ldc4 * 16) = *(int4*)ph;
            }
        } else {
#pragma unroll
            for (int it = 0; it < 2; it++) {
                int r = ldr + it * 64;
                CP16(s + r * 80 + ldc4 * 16, gA + (size_t)r * KR4 + c * 4 + ldc4);
            }
        }
        // B: 64 rows x 4 int4 = 256 int4, one per thread
        CP16(s + MATA + ldr * 80 + ldc4 * 16, gBh + (size_t)ldr * KR4 + c * 4 + ldc4);
        CPC();
    };

    float acc[2][4][4];
#pragma unroll
    for (int i = 0; i < 2; i++)
#pragma unroll
        for (int j = 0; j < 4; j++)
#pragma unroll
            for (int r = 0; r < 4; r++) acc[i][j][r] = 0.f;

    int aRow  = warpM * 32 + (lane & 15);
    int aColB = (lane >> 4) * 16;
    int bRow  = warpN * 32 + (lane & 7) + ((lane >> 4) << 3);
    int bColB = ((lane >> 3) & 1) * 16;

    load_stage(0, 0);

#pragma unroll 1
    for (int c = 0; c < NCH; c++) {
        CPW(0);                             // drain chunk c's loads
        __syncthreads();                    // all warps done reading buffer (c-1)&1
        if (c + 1 < NCH) load_stage(c + 1, (c + 1) & 1);

        uint32_t sA = sb32 + (c & 1) * STAGE;
        uint32_t sB = sA + MATA;
#pragma unroll
        for (int ks = 0; ks < 2; ks++) {
            uint32_t ah[2][4], bh[4][2];
#pragma unroll
            for (int mi2 = 0; mi2 < 2; mi2++) {
                uint32_t addr = sA + (aRow + mi2 * 16) * 80 + aColB + ks * 32;
                LDSM_X4(ah[mi2][0], ah[mi2][1], ah[mi2][2], ah[mi2][3], addr);
            }
#pragma unroll
            for (int nj2 = 0; nj2 < 2; nj2++) {
                uint32_t addr = sB + (bRow + nj2 * 16) * 80 + bColB + ks * 32;
                LDSM_X4(bh[nj2 * 2][0], bh[nj2 * 2][1], bh[nj2 * 2 + 1][0], bh[nj2 * 2 + 1][1], addr);
            }
#pragma unroll
            for (int mi2 = 0; mi2 < 2; mi2++)
#pragma unroll
                for (int nj = 0; nj < 4; nj++)
                    MMA_F16(acc[mi2][nj], ah[mi2][0], ah[mi2][1], ah[mi2][2], ah[mi2][3],
                            bh[nj][0], bh[nj][1]);
        }
    }
    // NCH even in both instantiations: last chunk used buffer 1; red[] uses buffer 0.

    // epilogue: store Y and accumulate column stats
    int g = lane >> 2, tig = lane & 3;
#pragma unroll
    for (int mi2 = 0; mi2 < 2; mi2++) {
        int r0 = m0 + warpM * 32 + mi2 * 16 + g;
#pragma unroll
        for (int nj = 0; nj < 4; nj++) {
            int cc = n0 + warpN * 32 + nj * 8 + 2 * tig;
            *(float2*)&Y[(size_t)r0 * ldc + cc] =
                make_float2(acc[mi2][nj][0], acc[mi2][nj][1]);
            *(float2*)&Y[(size_t)(r0 + 8) * ldc + cc] =
                make_float2(acc[mi2][nj][2], acc[mi2][nj][3]);
        }
    }
    float* red = (float*)smem;              // [0:64)=sum, [64:128)=sumsq
    if (tid < 128) red[tid] = 0.f;
    __syncthreads();
#pragma unroll
    for (int nj = 0; nj < 4; nj++)
#pragma unroll
        for (int half = 0; half < 2; half++) {
            int cloc = warpN * 32 + nj * 8 + 2 * tig + half;
            float s = 0.f, q = 0.f;
#pragma unroll
            for (int mi2 = 0; mi2 < 2; mi2++) {
                float v0 = acc[mi2][nj][half], v1 = acc[mi2][nj][2 + half];
                s += v0 + v1;
                q = fmaf(v0, v0, fmaf(v1, v1, q));
            }
            atomicAdd(&red[cloc], s);
            atomicAdd(&red[64 + cloc], q);
        }
    __syncthreads();
    if (tid < 64) {
        atomicAdd(&osum[n0 + tid], red[tid]);
        atomicAdd(&osq[n0 + tid], red[64 + tid]);
    }
}

__global__ void finalize_kernel(const float* __restrict__ sum, const float* __restrict__ sq,
                                const float* __restrict__ g, const float* __restrict__ be,
                                float* __restrict__ sc, float* __restrict__ sh)
{
    int c = threadIdx.x;
    float mean = sum[c] * (1.f / MM);
    float var  = sq[c] * (1.f / MM) - mean * mean;
    float s = g[c] * rsqrtf(var + 1e-5f);
    sc[c] = s;
    sh[c] = fmaf(-mean, s, be[c]);
}

// ---------------- BN2 + ReLU + transpose to out[b][c][n] ----------------
__global__ void writeout_kernel(float* __restrict__ out)
{
    __shared__ float tile[32][33];
    int b  = blockIdx.z;
    int n0 = blockIdx.x * 32, c0 = blockIdx.y * 32;
    int tx = threadIdx.x, ty = threadIdx.y;
#pragma unroll
    for (int i = 0; i < 4; i++) {
        int n = n0 + ty + i * 8;
        float v = g_Y2[((size_t)b * NN + n) * H2 + c0 + tx];
        v = fmaxf(fmaf(v, g_sc2[c0 + tx], g_sh2[c0 + tx]), 0.f);
        tile[ty + i * 8][tx] = v;
    }
    __syncthreads();
#pragma unroll
    for (int i = 0; i < 4; i++) {
        int c = c0 + ty + i * 8;
        out[((size_t)b * H2 + c) * NN + n0 + tx] = tile[tx][ty + i * 8];
    }
}

// ---------------- launch ----------------
extern "C" void kernel_launch(void* const* d_in, const int* in_sizes, int n_in,
                              void* d_out, int out_size)
{
    const float* xyz1    = (const float*)d_in[0];
    const float* xyz2    = (const float*)d_in[1];
    const float* points1 = (const float*)d_in[2];
    const float* points2 = (const float*)d_in[3];
    const float* W1  = (const float*)d_in[4];
    const float* g1  = (const float*)d_in[6];
    const float* be1 = (const float*)d_in[7];
    const float* W2  = (const float*)d_in[8];
    const float* g2  = (const float*)d_in[10];
    const float* be2 = (const float*)d_in[11];
    float* out = (float*)d_out;

    float *pY1, *pY2;
    float *psum1, *psq1, *psum2, *psq2, *psc1, *psh1, *psc2, *psh2;
    __half *pXh, *pW1h, *pW2h;
    cudaGetSymbolAddress((void**)&pY1,  g_Y1);
    cudaGetSymbolAddress((void**)&pY2,  g_Y2);
    cudaGetSymbolAddress((void**)&pXh,  g_Xh);
    cudaGetSymbolAddress((void**)&pW1h, g_W1h);
    cudaGetSymbolAddress((void**)&pW2h, g_W2h);
    cudaGetSymbolAddress((void**)&psum1, g_sum1);
    cudaGetSymbolAddress((void**)&psq1,  g_sq1);
    cudaGetSymbolAddress((void**)&psum2, g_sum2);
    cudaGetSymbolAddress((void**)&psq2,  g_sq2);
    cudaGetSymbolAddress((void**)&psc1,  g_sc1);
    cudaGetSymbolAddress((void**)&psh1,  g_sh1);
    cudaGetSymbolAddress((void**)&psc2,  g_sc2);
    cudaGetSymbolAddress((void**)&psh2,  g_sh2);

    // dynamic smem: 2 stages x (128+64) rows x 80B (+2KB BN tables for AFBN)
    const int smem_g1 = 2 * (128 + 64) * 80;              // 30720
    const int smem_g2 = 2 * (128 + 64) * 80 + 2 * H1 * 4; // 32768
    cudaFuncSetAttribute(tc_gemm_kernel<INCH, false>,
                         cudaFuncAttributeMaxDynamicSharedMemorySize, smem_g1);
    cudaFuncSetAttribute(tc_gemm_kernel<H1, true>,
                         cudaFuncAttributeMaxDynamicSharedMemorySize, smem_g2);

    // 1: fused producers (weights round + stats zero | P2T transpose | X cols 0:128)
    prep_kernel<<<12800, 256>>>(W1, W2, points1, points2);
    // 2: knn
    knn_kernel<<<dim3(NN / 128, BB), 128>>>(xyz1, xyz2);
    // 3: interp -> X cols 128:384
    interp_kernel<<<dim3(NN / 32, BB), 256>>>();
    // 4: GEMM1 (profiled slot), grid (512, 4)
    tc_gemm_kernel<INCH, false><<<dim3(MM / 128, H1 / 64), 256, smem_g1>>>(
        pXh, pW1h, nullptr, nullptr, pY1, H1, psum1, psq1);
    // 5: finalize BN1
    finalize_kernel<<<1, H1>>>(psum1, psq1, g1, be1, psc1, psh1);
    // 6: GEMM2 with fused BN1+ReLU+round on A, grid (512, 2)
    tc_gemm_kernel<H1, true><<<dim3(MM / 128, H2 / 64), 256, smem_g2>>>(
        pY1, pW2h, psc1, psh1, pY2, H2, psum2, psq2);
    // 7: finalize BN2
    finalize_kernel<<<1, H2>>>(psum2, psq2, g2, be2, psc2, psh2);
    // 8: BN2 + ReLU + transpose out
    writeout_kernel<<<dim3(NN / 32, H2 / 32, BB), dim3(32, 8)>>>(out);
}

// round 16
// speedup vs baseline: 1.2083x; 1.2083x over previous
#include <cuda_runtime.h>
#include <cuda_fp16.h>
#include <cstdint>

// Problem constants
#define BB   8
#define NN   8192
#define SS   2048
#define C1K  128
#define C2K  256
#define INCH 384            // C1 + C2
#define H1   256
#define H2   128
#define MM   (BB * NN)      // 65536 total points

// ---------------- scratch (static device globals; no allocation) ----------------
__device__ __half g_Xh [MM * (size_t)INCH];          // fp16-rounded concat(p1, interp)
__device__ __half g_W1h[H1 * INCH];
__device__ __half g_W2h[H2 * H1];
__device__ __half g_Y1 [MM * (size_t)H1];            // layer1 out, fp16 (pre-BN)
__device__ float g_Y2 [MM * (size_t)H2];
__device__ float g_P2T[BB * (size_t)SS * C2K];       // fp32 transposed points2
__device__ int   g_idx[MM * 3];
__device__ float g_wt [MM * 3];
__device__ float g_sum1[H1], g_sq1[H1], g_sum2[H2], g_sq2[H2];
__device__ float g_sc1 [H1], g_sh1[H1], g_sc2 [H2], g_sh2[H2];

// ---------------- PTX helpers (baseline sm_103 features only) ----------------
#define LDSM_X4(r0, r1, r2, r3, addr) \
    asm volatile("ldmatrix.sync.aligned.m8n8.x4.shared.b16 {%0,%1,%2,%3}, [%4];" \
        : "=r"(r0), "=r"(r1), "=r"(r2), "=r"(r3) : "r"(addr))

#define MMA_F16(d, a0, a1, a2, a3, b0, b1) \
    asm volatile("mma.sync.aligned.m16n8k16.row.col.f32.f16.f16.f32 " \
        "{%0,%1,%2,%3}, {%4,%5,%6,%7}, {%8,%9}, {%0,%1,%2,%3};" \
        : "+f"((d)[0]), "+f"((d)[1]), "+f"((d)[2]), "+f"((d)[3]) \
        : "r"(a0), "r"(a1), "r"(a2), "r"(a3), "r"(b0), "r"(b1))

#define CP16(dst, src) \
    asm volatile("cp.async.cg.shared.global [%0], [%1], 16;" :: "r"(dst), "l"(src) : "memory")
#define CPC() asm volatile("cp.async.commit_group;" ::: "memory")
#define CPW(n) asm volatile("cp.async.wait_group %0;" :: "n"(n) : "memory")

__device__ __forceinline__ uint32_t smem_to_u32(const void* p) {
    uint32_t a;
    asm("{ .reg .u64 t; cvta.to.shared.u64 t, %1; cvt.u32.u64 %0, t; }" : "=r"(a) : "l"(p));
    return a;
}
__device__ __forceinline__ uint32_t pack_h2(__half a, __half b) {
    __half2 v(a, b);
    return *(uint32_t*)&v;
}

// ================= fused producer kernel (R13 layout) =================
// blocks [0,512):      weight fp16 rounds + stats zero
// blocks [512,4608):   points2 [B,256,S] -> P2T [B,S,256] fp32 transpose
// blocks [4608,12800): points1 [B,128,N] -> Xh cols 0:128 (fp16 round)
__global__ __launch_bounds__(256) void prep_kernel(
    const float* __restrict__ W1, const float* __restrict__ W2,
    const float* __restrict__ points1, const float* __restrict__ points2)
{
    __shared__ float tile[32][33];
    int bx = blockIdx.x;
    int tid = threadIdx.x;
    if (bx < 512) {
        if (bx == 0) {
            g_sum1[tid] = 0.f; g_sq1[tid] = 0.f;
            if (tid < H2) { g_sum2[tid] = 0.f; g_sq2[tid] = 0.f; }
        }
        int i = bx * 256 + tid;
        if (i < H1 * INCH) {
            g_W1h[i] = __float2half(W1[i]);
        } else {
            int j = i - H1 * INCH;
            g_W2h[j] = __float2half(W2[j]);
        }
        return;
    }
    int tx = tid & 31, ty = tid >> 5;
    if (bx < 4608) {
        int t = bx - 512;
        int b = t >> 9, rem = t & 511;
        int l0 = (rem & 63) * 32, c0 = (rem >> 6) * 32;
        const float* s = points2 + (size_t)b * C2K * SS;
        float* d = g_P2T + (size_t)b * SS * C2K;
#pragma unroll
        for (int i = 0; i < 4; i++)
            tile[ty + i * 8][tx] = s[(size_t)(c0 + ty + i * 8) * SS + l0 + tx];
        __syncthreads();
#pragma unroll
        for (int i = 0; i < 4; i++)
            d[(size_t)(l0 + ty + i * 8) * C2K + c0 + tx] = tile[tx][ty + i * 8];
    } else {
        int t = bx - 4608;
        int b = t >> 10, rem = t & 1023;
        int l0 = (rem & 255) * 32, c0 = (rem >> 8) * 32;
        const float* s = points1 + (size_t)b * C1K * NN;
#pragma unroll
        for (int i = 0; i < 4; i++)
            tile[ty + i * 8][tx] = s[(size_t)(c0 + ty + i * 8) * NN + l0 + tx];
        __syncthreads();
#pragma unroll
        for (int i = 0; i < 4; i++) {
            int l = l0 + ty + i * 8;
            size_t o = ((size_t)b * NN + l) * INCH + c0 + tx;
            g_Xh[o] = __float2half(tile[tx][ty + i * 8]);
        }
    }
}

// ---------------- 3-NN, smem resident, dual interleaved trackers (fp32) ------
__global__ void knn_kernel(const float* __restrict__ xyz1, const float* __restrict__ xyz2)
{
    __shared__ float4 sq[SS];
    int b = blockIdx.y;
    const float* x2 = xyz2 + (size_t)b * 3 * SS;
    for (int s = threadIdx.x; s < SS; s += blockDim.x) {
        float qx = x2[s], qy = x2[SS + s], qz = x2[2 * SS + s];
        sq[s] = make_float4(qx, qy, qz, qx * qx + qy * qy + qz * qz);
    }
    __syncthreads();

    int n = blockIdx.x * blockDim.x + threadIdx.x;
    const float* x1 = xyz1 + (size_t)b * 3 * NN;
    float px = x1[n], py = x1[NN + n], pz = x1[2 * NN + n];
    float mx = -2.f * px, my = -2.f * py, mz = -2.f * pz;
    float p2 = px * px + py * py + pz * pz;

    float a0 = 1e30f, a1 = 1e30f, a2 = 1e30f;
    float c0 = 1e30f, c1 = 1e30f, c2 = 1e30f;
    int   ia0 = 0, ia1 = 0, ia2 = 0, ib0 = 0, ib1 = 0, ib2 = 0;

#pragma unroll 4
    for (int s = 0; s < SS / 2; s++) {
        float4 qa = sq[s];
        float4 qb = sq[s + SS / 2];
        float tA = fmaf(mx, qa.x, fmaf(my, qa.y, fmaf(mz, qa.z, qa.w)));
        float tB = fmaf(mx, qb.x, fmaf(my, qb.y, fmaf(mz, qb.z, qb.w)));
        if (tA < a2) {
            if (tA < a1) {
                a2 = a1; ia2 = ia1;
                if (tA < a0) { a1 = a0; ia1 = ia0; a0 = tA; ia0 = s; }
                else         { a1 = tA; ia1 = s; }
            } else { a2 = tA; ia2 = s; }
        }
        if (tB < c2) {
            if (tB < c1) {
                c2 = c1; ib2 = ib1;
                if (tB < c0) { c1 = c0; ib1 = ib0; c0 = tB; ib0 = s + SS / 2; }
                else         { c1 = tB; ib1 = s + SS / 2; }
            } else { c2 = tB; ib2 = s + SS / 2; }
        }
    }
    float mv[3] = {c0, c1, c2};
    int   mi[3] = {ib0, ib1, ib2};
#pragma unroll
    for (int t = 0; t < 3; t++) {
        float v = mv[t]; int ix = mi[t];
        if (v < a2) {
            if (v < a1) {
                a2 = a1; ia2 = ia1;
                if (v < a0) { a1 = a0; ia1 = ia0; a0 = v; ia0 = ix; }
                else        { a1 = v;  ia1 = ix; }
            } else { a2 = v; ia2 = ix; }
        }
    }
    float e0 = a0 + p2, e1 = a1 + p2, e2 = a2 + p2;
    float r0 = 1.f / (e0 + 1e-8f), r1 = 1.f / (e1 + 1e-8f), r2 = 1.f / (e2 + 1e-8f);
    float rs = 1.f / (r0 + r1 + r2);
    size_t base = ((size_t)b * NN + n) * 3;
    g_idx[base] = ia0; g_idx[base + 1] = ia1; g_idx[base + 2] = ia2;
    g_wt [base] = r0 * rs; g_wt[base + 1] = r1 * rs; g_wt[base + 2] = r2 * rs;
}

// ---------------- weighted gather of 3 rows from P2T -> Xh[:,128:384] --------
__global__ void interp_kernel()
{
    int b  = blockIdx.y;
    int c  = threadIdx.x;
    int n0 = blockIdx.x * 32;
    const float* p2t = g_P2T + (size_t)b * SS * C2K;
#pragma unroll 4
    for (int r = 0; r < 32; r++) {
        size_t m = (size_t)b * NN + n0 + r;
        int   j0 = g_idx[m * 3], j1 = g_idx[m * 3 + 1], j2 = g_idx[m * 3 + 2];
        float w0 = g_wt[m * 3], w1 = g_wt[m * 3 + 1], w2 = g_wt[m * 3 + 2];
        float v = w0 * p2t[(size_t)j0 * C2K + c]
                + w1 * p2t[(size_t)j1 * C2K + c]
                + w2 * p2t[(size_t)j2 * C2K + c];
        g_Xh[m * INCH + C1K + c] = __float2half(v);
    }
}

// ================= mma.sync fp16 GEMM (R13 config; optional fp16 output) ======
// 128x128 CTA tile, 8 warps (2m x 4n), warp tile 64x32, 2 CTAs/SM, 2-stage cp.async.
// C = Ah * Bh. Bias dropped (cancels in BN); column stats fused (fp32 acc).
// AFBN: A source is fp16 Y1; BN1+ReLU+fp16-round applied in register staging.
// HOUT: store Y as fp16 (packed half2); else fp32.
template <int K, bool AFBN, bool HOUT>
__global__ __launch_bounds__(256, 2) void tc_gemm_kernel(
    const void* __restrict__ Asrc,
    const __half* __restrict__ Bh,
    const float* __restrict__ sc, const float* __restrict__ sh,
    void* __restrict__ Yout, int ldc,
    float* __restrict__ osum, float* __restrict__ osq)
{
    constexpr int NCH   = K / 32;
    constexpr int KR4   = K / 8;           // int4 per fp16 row
    constexpr int MAT   = 128 * 80;        // bytes per smem matrix (padded)
    constexpr int STAGE = 2 * MAT;         // A, Bh

    extern __shared__ char smem[];
    uint32_t sb32 = smem_to_u32(smem);
    float* ssc = (float*)(smem + 2 * STAGE);
    float* ssh = ssc + K;

    int tid = threadIdx.x;
    int lane = tid & 31, wid = tid >> 5;
    int warpM = wid >> 2, warpN = wid & 3;
    int m0 = blockIdx.x * 128;
    int n0 = blockIdx.y * 128;

    const int4* gA = (const int4*)Asrc + (size_t)m0 * KR4;   // fp16 rows (both paths)
    const int4* gBh = (const int4*)Bh + (size_t)n0 * KR4;

    if (AFBN) {
        for (int i = tid; i < K; i += 256) { ssc[i] = sc[i]; ssh[i] = sh[i]; }
        __syncthreads();
    }

    int ldr = tid >> 2, ldc4 = tid & 3;

    auto load_stage = [&](int c, int stage) {
        uint32_t s = sb32 + stage * STAGE;
        if (AFBN) {
            // A is fp16 (pre-BN Y1): load 8 halves, BN+ReLU+round in registers
            char* sp = smem + stage * STAGE;
            int k0 = c * 32 + ldc4 * 8;
            float4 s0 = *(const float4*)&ssc[k0], s1 = *(const float4*)&ssc[k0 + 4];
            float4 t0 = *(const float4*)&ssh[k0], t1 = *(const float4*)&ssh[k0 + 4];
#pragma unroll
            for (int it = 0; it < 2; it++) {
                int r = ldr + it * 64;
                int4 v = gA[(size_t)r * KR4 + c * 4 + ldc4];
                __half2* hp = (__half2*)&v;
                float2 f0 = __half22float2(hp[0]);
                float2 f1 = __half22float2(hp[1]);
                float2 f2 = __half22float2(hp[2]);
                float2 f3 = __half22float2(hp[3]);
                uint32_t ph[4];
                ph[0] = pack_h2(__float2half(fmaxf(fmaf(f0.x, s0.x, t0.x), 0.f)),
                                __float2half(fmaxf(fmaf(f0.y, s0.y, t0.y), 0.f)));
                ph[1] = pack_h2(__float2half(fmaxf(fmaf(f1.x, s0.z, t0.z), 0.f)),
                                __float2half(fmaxf(fmaf(f1.y, s0.w, t0.w), 0.f)));
                ph[2] = pack_h2(__float2half(fmaxf(fmaf(f2.x, s1.x, t1.x), 0.f)),
                                __float2half(fmaxf(fmaf(f2.y, s1.y, t1.y), 0.f)));
                ph[3] = pack_h2(__float2half(fmaxf(fmaf(f3.x, s1.z, t1.z), 0.f)),
                                __float2half(fmaxf(fmaf(f3.y, s1.w, t1.w), 0.f)));
                *(int4*)(sp + r * 80 + ldc4 * 16) = *(int4*)ph;
            }
        } else {
#pragma unroll
            for (int it = 0; it < 2; it++) {
                int r = ldr + it * 64;
                CP16(s + r * 80 + ldc4 * 16, gA + (size_t)r * KR4 + c * 4 + ldc4);
            }
        }
#pragma unroll
        for (int it = 0; it < 2; it++) {
            int r = ldr + it * 64;
            CP16(s + MAT + r * 80 + ldc4 * 16, gBh + (size_t)r * KR4 + c * 4 + ldc4);
        }
        CPC();
    };

    float acc[4][4][4];
#pragma unroll
    for (int i = 0; i < 4; i++)
#pragma unroll
        for (int j = 0; j < 4; j++)
#pragma unroll
            for (int r = 0; r < 4; r++) acc[i][j][r] = 0.f;

    int aRow  = warpM * 64 + (lane & 15);
    int aColB = (lane >> 4) * 16;
    int bRow  = warpN * 32 + (lane & 7) + ((lane >> 4) << 3);
    int bColB = ((lane >> 3) & 1) * 16;

    load_stage(0, 0);

#pragma unroll 1
    for (int c = 0; c < NCH; c++) {
        CPW(0);                            // drain chunk c's loads
        __syncthreads();                   // all warps done reading buffer (c-1)&1
        if (c + 1 < NCH) load_stage(c + 1, (c + 1) & 1);

        uint32_t sA = sb32 + (c & 1) * STAGE;
        uint32_t sB = sA + MAT;
#pragma unroll
        for (int ks = 0; ks < 2; ks++) {
            uint32_t ah[4][4], bh[4][2];
#pragma unroll
            for (int mi2 = 0; mi2 < 4; mi2++) {
                uint32_t addr = sA + (aRow + mi2 * 16) * 80 + aColB + ks * 32;
                LDSM_X4(ah[mi2][0], ah[mi2][1], ah[mi2][2], ah[mi2][3], addr);
            }
#pragma unroll
            for (int nj2 = 0; nj2 < 2; nj2++) {
                uint32_t addr = sB + (bRow + nj2 * 16) * 80 + bColB + ks * 32;
                LDSM_X4(bh[nj2 * 2][0], bh[nj2 * 2][1], bh[nj2 * 2 + 1][0], bh[nj2 * 2 + 1][1], addr);
            }
#pragma unroll
            for (int mi2 = 0; mi2 < 4; mi2++)
#pragma unroll
                for (int nj = 0; nj < 4; nj++)
                    MMA_F16(acc[mi2][nj], ah[mi2][0], ah[mi2][1], ah[mi2][2], ah[mi2][3],
                            bh[nj][0], bh[nj][1]);
        }
    }
    // NCH even in both instantiations: last chunk used buffer 1; red[] uses buffer 0.

    // epilogue: store Y (fp16 or fp32) and accumulate column stats (fp32 acc)
    int g = lane >> 2, tig = lane & 3;
#pragma unroll
    for (int mi2 = 0; mi2 < 4; mi2++) {
        int r0 = m0 + warpM * 64 + mi2 * 16 + g;
#pragma unroll
        for (int nj = 0; nj < 4; nj++) {
            int cc = n0 + warpN * 32 + nj * 8 + 2 * tig;
            if (HOUT) {
                __half* Yh = (__half*)Yout;
                *(uint32_t*)&Yh[(size_t)r0 * ldc + cc] =
                    pack_h2(__float2half(acc[mi2][nj][0]), __float2half(acc[mi2][nj][1]));
                *(uint32_t*)&Yh[(size_t)(r0 + 8) * ldc + cc] =
                    pack_h2(__float2half(acc[mi2][nj][2]), __float2half(acc[mi2][nj][3]));
            } else {
                float* Yf = (float*)Yout;
                *(float2*)&Yf[(size_t)r0 * ldc + cc] =
                    make_float2(acc[mi2][nj][0], acc[mi2][nj][1]);
                *(float2*)&Yf[(size_t)(r0 + 8) * ldc + cc] =
                    make_float2(acc[mi2][nj][2], acc[mi2][nj][3]);
            }
        }
    }
    float* red = (float*)smem;
    if (tid < 128) { red[tid] = 0.f; red[tid + 128] = 0.f; }
    __syncthreads();
#pragma unroll
    for (int nj = 0; nj < 4; nj++)
#pragma unroll
        for (int half = 0; half < 2; half++) {
            int cloc = warpN * 32 + nj * 8 + 2 * tig + half;
            float s = 0.f, q = 0.f;
#pragma unroll
            for (int mi2 = 0; mi2 < 4; mi2++) {
                float v0 = acc[mi2][nj][half], v1 = acc[mi2][nj][2 + half];
                s += v0 + v1;
                q = fmaf(v0, v0, fmaf(v1, v1, q));
            }
            atomicAdd(&red[cloc], s);
            atomicAdd(&red[128 + cloc], q);
        }
    __syncthreads();
    if (tid < 128) {
        atomicAdd(&osum[n0 + tid], red[tid]);
        atomicAdd(&osq[n0 + tid], red[128 + tid]);
    }
}

__global__ void finalize_kernel(const float* __restrict__ sum, const float* __restrict__ sq,
                                const float* __restrict__ g, const float* __restrict__ be,
                                float* __restrict__ sc, float* __restrict__ sh)
{
    int c = threadIdx.x;
    float mean = sum[c] * (1.f / MM);
    float var  = sq[c] * (1.f / MM) - mean * mean;
    float s = g[c] * rsqrtf(var + 1e-5f);
    sc[c] = s;
    sh[c] = fmaf(-mean, s, be[c]);
}

// ---------------- BN2 + ReLU + transpose to out[b][c][n] ----------------
__global__ void writeout_kernel(float* __restrict__ out)
{
    __shared__ float tile[32][33];
    int b  = blockIdx.z;
    int n0 = blockIdx.x * 32, c0 = blockIdx.y * 32;
    int tx = threadIdx.x, ty = threadIdx.y;
#pragma unroll
    for (int i = 0; i < 4; i++) {
        int n = n0 + ty + i * 8;
        float v = g_Y2[((size_t)b * NN + n) * H2 + c0 + tx];
        v = fmaxf(fmaf(v, g_sc2[c0 + tx], g_sh2[c0 + tx]), 0.f);
        tile[ty + i * 8][tx] = v;
    }
    __syncthreads();
#pragma unroll
    for (int i = 0; i < 4; i++) {
        int c = c0 + ty + i * 8;
        out[((size_t)b * H2 + c) * NN + n0 + tx] = tile[tx][ty + i * 8];
    }
}

// ---------------- launch ----------------
extern "C" void kernel_launch(void* const* d_in, const int* in_sizes, int n_in,
                              void* d_out, int out_size)
{
    const float* xyz1    = (const float*)d_in[0];
    const float* xyz2    = (const float*)d_in[1];
    const float* points1 = (const float*)d_in[2];
    const float* points2 = (const float*)d_in[3];
    const float* W1  = (const float*)d_in[4];
    const float* g1  = (const float*)d_in[6];
    const float* be1 = (const float*)d_in[7];
    const float* W2  = (const float*)d_in[8];
    const float* g2  = (const float*)d_in[10];
    const float* be2 = (const float*)d_in[11];
    float* out = (float*)d_out;

    float *pY2;
    float *psum1, *psq1, *psum2, *psq2, *psc1, *psh1, *psc2, *psh2;
    __half *pXh, *pY1, *pW1h, *pW2h;
    cudaGetSymbolAddress((void**)&pY1,  g_Y1);
    cudaGetSymbolAddress((void**)&pY2,  g_Y2);
    cudaGetSymbolAddress((void**)&pXh,  g_Xh);
    cudaGetSymbolAddress((void**)&pW1h, g_W1h);
    cudaGetSymbolAddress((void**)&pW2h, g_W2h);
    cudaGetSymbolAddress((void**)&psum1, g_sum1);
    cudaGetSymbolAddress((void**)&psq1,  g_sq1);
    cudaGetSymbolAddress((void**)&psum2, g_sum2);
    cudaGetSymbolAddress((void**)&psq2,  g_sq2);
    cudaGetSymbolAddress((void**)&psc1,  g_sc1);
    cudaGetSymbolAddress((void**)&psh1,  g_sh1);
    cudaGetSymbolAddress((void**)&psc2,  g_sc2);
    cudaGetSymbolAddress((void**)&psh2,  g_sh2);

    // dynamic smem: 2 stages x 2 matrices x 128 rows x 80B (+2KB BN tables for AFBN)
    const int smem_g1 = 2 * 2 * 128 * 80;                 // 40960
    const int smem_g2 = 2 * 2 * 128 * 80 + 2 * H1 * 4;    // 43008
    cudaFuncSetAttribute(tc_gemm_kernel<INCH, false, true>,
                         cudaFuncAttributeMaxDynamicSharedMemorySize, smem_g1);
    cudaFuncSetAttribute(tc_gemm_kernel<H1, true, false>,
                         cudaFuncAttributeMaxDynamicSharedMemorySize, smem_g2);

    // 1: fused producers (weights round + stats zero | P2T transpose | X cols 0:128)
    prep_kernel<<<12800, 256>>>(W1, W2, points1, points2);
    // 2: knn
    knn_kernel<<<dim3(NN / 128, BB), 128>>>(xyz1, xyz2);
    // 3: interp -> X cols 128:384
    interp_kernel<<<dim3(NN / 32, BB), 256>>>();
    // 4: GEMM1 (profiled slot) -> Y1 fp16
    tc_gemm_kernel<INCH, false, true><<<dim3(MM / 128, H1 / 128), 256, smem_g1>>>(
        pXh, pW1h, nullptr, nullptr, pY1, H1, psum1, psq1);
    // 5: finalize BN1
    finalize_kernel<<<1, H1>>>(psum1, psq1, g1, be1, psc1, psh1);
    // 6: GEMM2 with fused BN1+ReLU+round on fp16 A -> Y2 fp32
    tc_gemm_kernel<H1, true, false><<<dim3(MM / 128, H2 / 128), 256, smem_g2>>>(
        pY1, pW2h, psc1, psh1, pY2, H2, psum2, psq2);
    // 7: finalize BN2
    finalize_kernel<<<1, H2>>>(psum2, psq2, g2, be2, psc2, psh2);
    // 8: BN2 + ReLU + transpose out
    writeout_kernel<<<dim3(NN / 32, H2 / 32, BB), dim3(32, 8)>>>(out);
}